// round 2
// baseline (speedup 1.0000x reference)
#include <cuda_runtime.h>
#include <cuda_bf16.h>

#define T_LEN   32768
#define C_LEN   512
#define B_LEN   8
#define KSZ     12
#define PADW    6
#define TILE    1024
#define NTHREADS 256
#define EPS_F   1e-9f

// Fused SnakeBeta + reflect-pad + depthwise 12-tap conv.
// One block = one TILE-wide chunk of one (b,c) row.
// out[t] = sum_k snake(y_reflect[t + k - PAD]) * filt[k],  t in [0, T]
__global__ __launch_bounds__(NTHREADS)
void snake_aa_kernel(const float* __restrict__ x,
                     const float* __restrict__ alpha,
                     const float* __restrict__ beta,
                     const float* __restrict__ filt,
                     float* __restrict__ out) {
    __shared__ float s[TILE + KSZ];  // TILE + 11 used

    const int row = blockIdx.y;        // row = b*C + c
    const int c   = row & (C_LEN - 1); // C = 512 (power of 2)
    const int t0  = blockIdx.x * TILE;

    const float a    = expf(alpha[c]);
    const float binv = 1.0f / (expf(beta[c]) + EPS_F);

    const float* __restrict__ xr = x + (size_t)row * T_LEN;

    // Load TILE + K - 1 halo elements, apply snake, reflect at edges.
    #pragma unroll
    for (int j = threadIdx.x; j < TILE + KSZ - 1; j += NTHREADS) {
        int g = t0 - PADW + j;
        if (g < 0) g = -g;                       // left reflect (excl. edge)
        if (g >= T_LEN) g = 2 * (T_LEN - 1) - g; // right reflect
        float v  = xr[g];
        float sn = sinf(v * a);
        s[j] = fmaf(sn * sn, binv, v);
    }
    __syncthreads();

    // Filter taps: 12 L1-resident loads per thread.
    float f[KSZ];
    #pragma unroll
    for (int k = 0; k < KSZ; ++k) f[k] = __ldg(&filt[k]);

    float* __restrict__ orow = out + (size_t)row * (T_LEN + 1);

    #pragma unroll
    for (int t = threadIdx.x; t < TILE; t += NTHREADS) {
        const int gt = t0 + t;
        if (gt <= T_LEN) {
            float acc = 0.0f;
            #pragma unroll
            for (int k = 0; k < KSZ; ++k)
                acc = fmaf(s[t + k], f[k], acc);
            orow[gt] = acc;
        }
    }
}

extern "C" void kernel_launch(void* const* d_in, const int* in_sizes, int n_in,
                              void* d_out, int out_size) {
    const float* x     = (const float*)d_in[0];
    const float* alpha = (const float*)d_in[1];
    const float* beta  = (const float*)d_in[2];
    const float* filt  = (const float*)d_in[3];
    float* out = (float*)d_out;

    const int n_chunks = (T_LEN + 1 + TILE - 1) / TILE;  // 33
    dim3 grid(n_chunks, B_LEN * C_LEN);                  // (33, 4096)
    snake_aa_kernel<<<grid, NTHREADS>>>(x, alpha, beta, filt, out);
}

// round 3
// speedup vs baseline: 1.5924x; 1.5924x over previous
#include <cuda_runtime.h>
#include <cuda_bf16.h>

#define T_LEN   32768
#define C_LEN   512
#define B_LEN   8
#define KSZ     12
#define TILE    2048
#define NT      256
#define RPT     8                    // outputs per thread (NT*RPT == TILE)
#define HALO    8                    // >= PAD(6), 8 keeps float4 alignment
#define SW      (TILE + 2 * HALO)    // 2064 smem words
#define EPS_F   1e-9f

__device__ __forceinline__ float snake(float v, float a, float binv) {
    float sn = __sinf(v * a);        // MUFU.SIN — |v*a| small, err << 1e-3
    return fmaf(sn * sn, binv, v);
}

__global__ __launch_bounds__(NT)
void snake_aa_kernel(const float* __restrict__ x,
                     const float* __restrict__ alpha,
                     const float* __restrict__ beta,
                     const float* __restrict__ filt,
                     float* __restrict__ out) {
    __shared__ float s[SW];      // snake-activated input tile + halo
    __shared__ float so[TILE];   // output staging tile

    const int row = blockIdx.y;          // b*C + c
    const int c   = row & (C_LEN - 1);
    const int t0  = blockIdx.x * TILE;
    const int tid = threadIdx.x;

    const float a    = expf(alpha[c]);
    const float binv = 1.0f / (expf(beta[c]) + EPS_F);

    const float* __restrict__ xr = x + (size_t)row * T_LEN;

    // ---- Phase 1: load + snake into smem. Vector path for interior chunks. ----
    if (t0 >= HALO && t0 - HALO + SW <= T_LEN) {
        const float4* __restrict__ xv = (const float4*)(xr + t0 - HALO);
        for (int j4 = tid; j4 < SW / 4; j4 += NT) {   // 516 float4s
            float4 v = __ldg(&xv[j4]);
            float4 r;
            r.x = snake(v.x, a, binv);
            r.y = snake(v.y, a, binv);
            r.z = snake(v.z, a, binv);
            r.w = snake(v.w, a, binv);
            ((float4*)s)[j4] = r;
        }
    } else {
        for (int j = tid; j < SW; j += NT) {
            int g = t0 - HALO + j;
            if (g < 0) g = -g;                        // left reflect
            if (g >= T_LEN) g = 2 * (T_LEN - 1) - g;  // right reflect
            s[j] = snake(xr[g], a, binv);
        }
    }
    __syncthreads();

    // ---- Phase 2a: 8 consecutive outputs/thread via register sliding window ----
    float f[KSZ];
    #pragma unroll
    for (int k = 0; k < KSZ; ++k) f[k] = __ldg(&filt[k]);

    const int u0 = tid * RPT;
    // output u0+r needs s[u0+r+2 .. u0+r+13]  (input g = t-6..t+5, smem shift +HALO)
    float w[RPT + KSZ - 1];
    #pragma unroll
    for (int i = 0; i < RPT + KSZ - 1; ++i) w[i] = s[u0 + 2 + i];

    float acc[RPT];
    #pragma unroll
    for (int r = 0; r < RPT; ++r) {
        float v = w[r] * f[0];
        #pragma unroll
        for (int k = 1; k < KSZ; ++k) v = fmaf(w[r + k], f[k], v);
        acc[r] = v;
    }
    float4* sov = (float4*)(so + u0);   // u0 % 8 == 0 -> 16B aligned
    sov[0] = make_float4(acc[0], acc[1], acc[2], acc[3]);
    sov[1] = make_float4(acc[4], acc[5], acc[6], acc[7]);
    __syncthreads();

    // ---- Phase 2b: coalesced copy-out (scalar; row stride T+1 is odd) ----
    float* __restrict__ orow = out + (size_t)row * (T_LEN + 1);
    #pragma unroll
    for (int k = 0; k < TILE / NT; ++k) {
        int j  = tid + k * NT;
        int gt = t0 + j;
        if (gt <= T_LEN) orow[gt] = so[j];
    }
}

extern "C" void kernel_launch(void* const* d_in, const int* in_sizes, int n_in,
                              void* d_out, int out_size) {
    const float* x     = (const float*)d_in[0];
    const float* alpha = (const float*)d_in[1];
    const float* beta  = (const float*)d_in[2];
    const float* filt  = (const float*)d_in[3];
    float* out = (float*)d_out;

    const int n_chunks = (T_LEN + 1 + TILE - 1) / TILE;   // 17
    dim3 grid(n_chunks, B_LEN * C_LEN);                   // (17, 4096)
    snake_aa_kernel<<<grid, NT>>>(x, alpha, beta, filt, out);
}

// round 4
// speedup vs baseline: 1.8779x; 1.1793x over previous
#include <cuda_runtime.h>
#include <cuda_bf16.h>

#define T_LEN   32768
#define C_LEN   512
#define B_LEN   8
#define KSZ     12
#define NT      256      // 8 warps per block
#define WTILE   256      // outputs per warp (32 lanes x 8)
#define BTILE   2048     // outputs per block
#define EPS_F   1e-9f
#define FULLM   0xFFFFFFFFu

__device__ __forceinline__ float snake(float v, float a, float binv) {
    float sn = __sinf(v * a);           // MUFU.SIN, err << 1e-3 tolerance
    return fmaf(sn * sn, binv, v);
}

// Main kernel: outputs [0, T_LEN) of every row. No reflect in the bulk path;
// inter-lane halo via shuffles, inter-warp halo via direct (L2-hot) loads.
__global__ __launch_bounds__(NT)
void snake_aa_main(const float* __restrict__ x,
                   const float* __restrict__ alpha,
                   const float* __restrict__ beta,
                   const float* __restrict__ filt,
                   float* __restrict__ out) {
    __shared__ float so[BTILE];          // output staging for coalesced stores

    const int row = blockIdx.y;          // b*C + c
    const int c   = row & (C_LEN - 1);
    const int t0  = blockIdx.x * BTILE;
    const int tid = threadIdx.x;
    const int wp  = tid >> 5;
    const int l   = tid & 31;

    const float a    = __expf(alpha[c]);
    const float binv = 1.0f / (__expf(beta[c]) + EPS_F);
    const float* __restrict__ xr = x + (size_t)row * T_LEN;

    const int w0   = t0 + wp * WTILE;    // warp's output tile start
    const int base = w0 + l * 8;         // this lane's 8 outputs

    // Own 8 inputs, snake-activated once each.
    float4 q0 = *(const float4*)(xr + base);
    float4 q1 = *(const float4*)(xr + base + 4);
    float v[8];
    v[0] = snake(q0.x, a, binv); v[1] = snake(q0.y, a, binv);
    v[2] = snake(q0.z, a, binv); v[3] = snake(q0.w, a, binv);
    v[4] = snake(q1.x, a, binv); v[5] = snake(q1.y, a, binv);
    v[6] = snake(q1.z, a, binv); v[7] = snake(q1.w, a, binv);

    // Halo: prev 6 from lane l-1, next 6 from lane l+1.
    float p[6], n[6];
    #pragma unroll
    for (int i = 0; i < 6; ++i) p[i] = __shfl_up_sync(FULLM, v[2 + i], 1);
    #pragma unroll
    for (int i = 0; i < 6; ++i) n[i] = __shfl_down_sync(FULLM, v[i], 1);

    // Warp-edge lanes fetch cross-warp halo from global (reflect at row ends).
    if (l == 0) {
        #pragma unroll
        for (int i = 0; i < 6; ++i) {
            int g = w0 - 6 + i;
            if (g < 0) g = -g;
            p[i] = snake(xr[g], a, binv);
        }
    }
    if (l == 31) {
        #pragma unroll
        for (int i = 0; i < 6; ++i) {
            int g = w0 + WTILE + i;
            if (g >= T_LEN) g = 2 * (T_LEN - 1) - g;
            n[i] = snake(xr[g], a, binv);
        }
    }

    float f[KSZ];
    #pragma unroll
    for (int k = 0; k < KSZ; ++k) f[k] = __ldg(&filt[k]);

    // Window wd[i] = snaked input[base - 6 + i], i in [0, 20)
    float wd[20];
    #pragma unroll
    for (int i = 0; i < 6; ++i) wd[i] = p[i];
    #pragma unroll
    for (int i = 0; i < 8; ++i) wd[6 + i] = v[i];
    #pragma unroll
    for (int i = 0; i < 6; ++i) wd[14 + i] = n[i];

    // 8 outputs: out[base + r] = sum_k f[k] * wd[r + k]
    float acc[8];
    #pragma unroll
    for (int r = 0; r < 8; ++r) {
        float s = wd[r] * f[0];
        #pragma unroll
        for (int k = 1; k < KSZ; ++k) s = fmaf(wd[r + k], f[k], s);
        acc[r] = s;
    }

    // Stage (8 consecutive per lane), then coalesced copy-out.
    float4* sp = (float4*)(so + wp * WTILE + l * 8);
    sp[0] = make_float4(acc[0], acc[1], acc[2], acc[3]);
    sp[1] = make_float4(acc[4], acc[5], acc[6], acc[7]);
    __syncthreads();

    float* __restrict__ orow = out + (size_t)row * (T_LEN + 1);
    #pragma unroll
    for (int k = 0; k < BTILE / NT; ++k) {
        int j = tid + k * NT;
        orow[t0 + j] = so[j];            // t0 + j < T_LEN always
    }
}

// Tail kernel: out[row][T_LEN] (the +1 output of the even-kernel conv).
__global__ void snake_aa_tail(const float* __restrict__ x,
                              const float* __restrict__ alpha,
                              const float* __restrict__ beta,
                              const float* __restrict__ filt,
                              float* __restrict__ out) {
    int row = blockIdx.x * blockDim.x + threadIdx.x;
    if (row >= B_LEN * C_LEN) return;
    int c = row & (C_LEN - 1);
    float a    = __expf(alpha[c]);
    float binv = 1.0f / (__expf(beta[c]) + EPS_F);
    const float* __restrict__ xr = x + (size_t)row * T_LEN;

    float accv = 0.0f;
    #pragma unroll
    for (int k = 0; k < KSZ; ++k) {
        int g = T_LEN - 6 + k;
        if (g >= T_LEN) g = 2 * (T_LEN - 1) - g;
        accv = fmaf(snake(xr[g], a, binv), __ldg(&filt[k]), accv);
    }
    out[(size_t)row * (T_LEN + 1) + T_LEN] = accv;
}

extern "C" void kernel_launch(void* const* d_in, const int* in_sizes, int n_in,
                              void* d_out, int out_size) {
    const float* x     = (const float*)d_in[0];
    const float* alpha = (const float*)d_in[1];
    const float* beta  = (const float*)d_in[2];
    const float* filt  = (const float*)d_in[3];
    float* out = (float*)d_out;

    dim3 grid(T_LEN / BTILE, B_LEN * C_LEN);   // (16, 4096)
    snake_aa_main<<<grid, NT>>>(x, alpha, beta, filt, out);
    snake_aa_tail<<<(B_LEN * C_LEN + 255) / 256, 256>>>(x, alpha, beta, filt, out);
}

// round 5
// speedup vs baseline: 1.9408x; 1.0335x over previous
#include <cuda_runtime.h>
#include <cuda_bf16.h>

#define T_LEN   32768
#define C_LEN   512
#define B_LEN   8
#define KSZ     12
#define NT      256      // 8 warps
#define RPT     16       // outputs per thread
#define WTILE   (32 * RPT)        // 512 outputs per warp
#define BTILE   (8 * WTILE)       // 4096 outputs per block
#define EPS_F   1e-9f
#define FULLM   0xFFFFFFFFu

__device__ __forceinline__ float snake(float v, float a, float binv) {
    float sn = __sinf(v * a);             // MUFU.SIN, |v*a| small, err << 1e-3
    return fmaf(sn * sn, binv, v);
}

__global__ __launch_bounds__(NT)
void snake_aa_kernel(const float* __restrict__ x,
                     const float* __restrict__ alpha,
                     const float* __restrict__ beta,
                     const float* __restrict__ filt,
                     float* __restrict__ out) {
    __shared__ float so[BTILE];           // output staging for coalesced stores

    const int row = blockIdx.y;           // b*C + c
    const int c   = row & (C_LEN - 1);
    const int t0  = blockIdx.x * BTILE;
    const int tid = threadIdx.x;
    const int wp  = tid >> 5;
    const int l   = tid & 31;

    const float a    = __expf(alpha[c]);
    const float binv = 1.0f / (__expf(beta[c]) + EPS_F);
    const float* __restrict__ xr = x + (size_t)row * T_LEN;

    const int w0   = t0 + wp * WTILE;     // warp tile start
    const int base = w0 + l * RPT;        // this lane's 16 outputs

    // Issue all 4 independent vector loads up front (MLP=4), streaming hint.
    const float4* __restrict__ xv = (const float4*)(xr + base);
    float4 q0 = __ldcs(&xv[0]);
    float4 q1 = __ldcs(&xv[1]);
    float4 q2 = __ldcs(&xv[2]);
    float4 q3 = __ldcs(&xv[3]);

    // wd[j] = snaked input[base - 6 + j], j in [0, 28)
    float wd[RPT + 2 * 6];
    wd[6]  = snake(q0.x, a, binv); wd[7]  = snake(q0.y, a, binv);
    wd[8]  = snake(q0.z, a, binv); wd[9]  = snake(q0.w, a, binv);
    wd[10] = snake(q1.x, a, binv); wd[11] = snake(q1.y, a, binv);
    wd[12] = snake(q1.z, a, binv); wd[13] = snake(q1.w, a, binv);
    wd[14] = snake(q2.x, a, binv); wd[15] = snake(q2.y, a, binv);
    wd[16] = snake(q2.z, a, binv); wd[17] = snake(q2.w, a, binv);
    wd[18] = snake(q3.x, a, binv); wd[19] = snake(q3.y, a, binv);
    wd[20] = snake(q3.z, a, binv); wd[21] = snake(q3.w, a, binv);

    // Inter-lane halo via shuffles: prev 6 from lane-1 (its wd[16..21]),
    // next 6 from lane+1 (its wd[6..11]).
    #pragma unroll
    for (int i = 0; i < 6; ++i) wd[i]      = __shfl_up_sync  (FULLM, wd[16 + i], 1);
    #pragma unroll
    for (int i = 0; i < 6; ++i) wd[22 + i] = __shfl_down_sync(FULLM, wd[6 + i],  1);

    // Warp-edge lanes: fetch cross-warp halo from global (L2-hot), reflect at row ends.
    if (l == 0) {
        #pragma unroll
        for (int i = 0; i < 6; ++i) {
            int g = w0 - 6 + i;
            if (g < 0) g = -g;
            wd[i] = snake(xr[g], a, binv);
        }
    }
    if (l == 31) {
        #pragma unroll
        for (int i = 0; i < 6; ++i) {
            int g = w0 + WTILE + i;
            if (g >= T_LEN) g = 2 * (T_LEN - 1) - g;
            wd[22 + i] = snake(xr[g], a, binv);
        }
    }

    float f[KSZ];
    #pragma unroll
    for (int k = 0; k < KSZ; ++k) f[k] = __ldg(&filt[k]);

    // 16 outputs: out[base + r] = sum_k f[k] * wd[r + k]
    float* sp = so + wp * WTILE + l * RPT;
    #pragma unroll
    for (int r4 = 0; r4 < RPT; r4 += 4) {
        float4 o;
        float s0 = wd[r4 + 0] * f[0];
        float s1 = wd[r4 + 1] * f[0];
        float s2 = wd[r4 + 2] * f[0];
        float s3 = wd[r4 + 3] * f[0];
        #pragma unroll
        for (int k = 1; k < KSZ; ++k) {
            s0 = fmaf(wd[r4 + 0 + k], f[k], s0);
            s1 = fmaf(wd[r4 + 1 + k], f[k], s1);
            s2 = fmaf(wd[r4 + 2 + k], f[k], s2);
            s3 = fmaf(wd[r4 + 3 + k], f[k], s3);
        }
        o.x = s0; o.y = s1; o.z = s2; o.w = s3;
        *(float4*)(sp + r4) = o;          // base%16==0 -> aligned
    }
    __syncthreads();

    // Coalesced copy-out (scalar: row stride T+1 = 32769 is odd).
    float* __restrict__ orow = out + (size_t)row * (T_LEN + 1);
    #pragma unroll
    for (int k = 0; k < BTILE / NT; ++k) {
        int j = tid + k * NT;
        __stcs(&orow[t0 + j], so[j]);
    }

    // Fused tail: out[row][T_LEN] (the +1 output), one thread of the last chunk.
    if (blockIdx.x == (T_LEN / BTILE) - 1 && tid == 0) {
        float accv = 0.0f;
        #pragma unroll
        for (int k = 0; k < KSZ; ++k) {
            int g = T_LEN - 6 + k;
            if (g >= T_LEN) g = 2 * (T_LEN - 1) - g;
            accv = fmaf(snake(xr[g], a, binv), f[k], accv);
        }
        orow[T_LEN] = accv;
    }
}

extern "C" void kernel_launch(void* const* d_in, const int* in_sizes, int n_in,
                              void* d_out, int out_size) {
    const float* x     = (const float*)d_in[0];
    const float* alpha = (const float*)d_in[1];
    const float* beta  = (const float*)d_in[2];
    const float* filt  = (const float*)d_in[3];
    float* out = (float*)d_out;

    dim3 grid(T_LEN / BTILE, B_LEN * C_LEN);   // (8, 4096)
    snake_aa_kernel<<<grid, NT>>>(x, alpha, beta, filt, out);
}